// round 3
// baseline (speedup 1.0000x reference)
#include <cuda_runtime.h>
#include <math.h>

// ---------------------------------------------------------------------------
// PoetryGPT forward: B=2, T=1024, D=1024, H=16, HD=64, L=8, V=32000, fp32
// ---------------------------------------------------------------------------
#define D_MODEL 1024
#define NHEAD   16
#define HDIM    64
#define SEQ     1024
#define NLAYER  8
#define BATCH   2
#define BT      (BATCH*SEQ)   // 2048
#define DFF     4096
#define VOCAB   32000

// ---- scratch (static device globals: allocation-guard safe) ----
__device__ float g_h   [(size_t)BT*D_MODEL];            // residual stream
__device__ float g_ln  [(size_t)BT*D_MODEL];            // layernorm output
__device__ float g_qkv [(size_t)BT*3*D_MODEL];          // fused QKV
__device__ float g_o   [(size_t)BT*D_MODEL];            // attention out (head-concat)
__device__ float g_f   [(size_t)BT*DFF];                // MLP hidden
__device__ float g_wqkv[(size_t)NLAYER*D_MODEL*3*D_MODEL]; // repacked QKV weights

// ---------------------------------------------------------------------------
// Repack Wq/Wk/Wv [L,H,D,HD] -> g_wqkv[L][D][3*D]  (col = w*1024 + h*64 + e)
// ---------------------------------------------------------------------------
__global__ void repack_kernel(const float* __restrict__ Wq,
                              const float* __restrict__ Wk,
                              const float* __restrict__ Wv)
{
    size_t i = (size_t)blockIdx.x * 256 + threadIdx.x;
    // i = ((((l*3 + w)*NHEAD + h)*D_MODEL + d)*HDIM + e)
    int e = (int)(i & 63);        size_t r = i >> 6;
    int d = (int)(r & 1023);      r >>= 10;
    int h = (int)(r & 15);        r >>= 4;
    int w = (int)(r % 3);
    int l = (int)(r / 3);
    const float* W = (w == 0) ? Wq : (w == 1) ? Wk : Wv;
    float v = W[(((size_t)l*NHEAD + h)*D_MODEL + d)*HDIM + e];
    g_wqkv[((size_t)l*D_MODEL + d)*(3*D_MODEL) + (size_t)w*D_MODEL + h*HDIM + e] = v;
}

// ---------------------------------------------------------------------------
// h = tok_emb[x] + pos_emb
// ---------------------------------------------------------------------------
__global__ void embed_kernel(const int* __restrict__ x,
                             const float* __restrict__ tok,
                             const float* __restrict__ pos)
{
    int i  = blockIdx.x * 256 + threadIdx.x;   // over BT*D
    int d  = i & (D_MODEL - 1);
    int bt = i >> 10;
    int t  = bt & (SEQ - 1);
    int id = x[bt];
    g_h[i] = tok[(size_t)id * D_MODEL + d] + pos[(size_t)t * D_MODEL + d];
}

// ---------------------------------------------------------------------------
// LayerNorm: one block per row of 1024, 256 threads x float4
// ---------------------------------------------------------------------------
__global__ __launch_bounds__(256)
void ln_kernel(const float* __restrict__ x, const float* __restrict__ gw,
               const float* __restrict__ bw, float* __restrict__ y)
{
    int row = blockIdx.x, tid = threadIdx.x;
    float4 v = ((const float4*)(x + (size_t)row * D_MODEL))[tid];
    float s = v.x + v.y + v.z + v.w;
    float q = v.x*v.x + v.y*v.y + v.z*v.z + v.w*v.w;
    #pragma unroll
    for (int o = 16; o > 0; o >>= 1) {
        s += __shfl_xor_sync(0xffffffffu, s, o);
        q += __shfl_xor_sync(0xffffffffu, q, o);
    }
    __shared__ float ssum[8], ssq[8];
    if ((tid & 31) == 0) { ssum[tid >> 5] = s; ssq[tid >> 5] = q; }
    __syncthreads();
    float ts = 0.f, tq = 0.f;
    #pragma unroll
    for (int i = 0; i < 8; i++) { ts += ssum[i]; tq += ssq[i]; }
    float mu   = ts * (1.f / D_MODEL);
    float var  = tq * (1.f / D_MODEL) - mu * mu;
    float rstd = rsqrtf(var + 1e-5f);
    float4 g4 = ((const float4*)gw)[tid];
    float4 b4 = ((const float4*)bw)[tid];
    float4 o4;
    o4.x = (v.x - mu) * rstd * g4.x + b4.x;
    o4.y = (v.y - mu) * rstd * g4.y + b4.y;
    o4.z = (v.z - mu) * rstd * g4.z + b4.z;
    o4.w = (v.w - mu) * rstd * g4.w + b4.w;
    ((float4*)(y + (size_t)row * D_MODEL))[tid] = o4;
}

// ---------------------------------------------------------------------------
// Generic SGEMM: C[M,N] = (RES? res : 0) + A[M,K]*B[K,N] + (BIAS? bias : 0)
// 128x128 tile, BK=8, 256 threads, 8x8 per thread.
// Requires: M%128==0, N%128==0, K%8==0 (true for all shapes here).
// ---------------------------------------------------------------------------
#define BM 128
#define BN 128
#define BK 8
#define TM 8
#define TN 8

template <bool BIAS, bool RELU, bool RES>
__global__ __launch_bounds__(256)
void sgemm(const float* __restrict__ A, const float* __restrict__ B,
           const float* __restrict__ bias, const float* __restrict__ res,
           float* __restrict__ C, int M, int N, int K)
{
    __shared__ float As[BK][BM];
    __shared__ float Bs[BK][BN];

    int tid = threadIdx.x;
    int tx  = tid & 15;        // 0..15 (cols)
    int ty  = tid >> 4;        // 0..15 (rows)
    int row0 = blockIdx.y * BM;
    int col0 = blockIdx.x * BN;

    int aRow  = tid >> 1;          // 0..127
    int aCol4 = (tid & 1) * 4;     // 0 or 4
    int bRow  = tid >> 5;          // 0..7
    int bCol4 = (tid & 31) * 4;    // 0..124

    const float* Aptr = A + (size_t)(row0 + aRow) * K + aCol4;
    const float* Bptr = B + (size_t)bRow * N + col0 + bCol4;

    float acc[TM][TN] = {};

    for (int k0 = 0; k0 < K; k0 += BK) {
        float4 av = *(const float4*)Aptr;
        float4 bv = *(const float4*)Bptr;
        Aptr += BK;
        Bptr += (size_t)BK * N;

        As[aCol4 + 0][aRow] = av.x;
        As[aCol4 + 1][aRow] = av.y;
        As[aCol4 + 2][aRow] = av.z;
        As[aCol4 + 3][aRow] = av.w;
        *(float4*)&Bs[bRow][bCol4] = bv;
        __syncthreads();

        #pragma unroll
        for (int kk = 0; kk < BK; kk++) {
            float4 a0 = *(const float4*)&As[kk][ty * TM];
            float4 a1 = *(const float4*)&As[kk][ty * TM + 4];
            float4 b0 = *(const float4*)&Bs[kk][tx * TN];
            float4 b1 = *(const float4*)&Bs[kk][tx * TN + 4];
            float ar[TM] = {a0.x, a0.y, a0.z, a0.w, a1.x, a1.y, a1.z, a1.w};
            float br[TN] = {b0.x, b0.y, b0.z, b0.w, b1.x, b1.y, b1.z, b1.w};
            #pragma unroll
            for (int i = 0; i < TM; i++)
                #pragma unroll
                for (int j = 0; j < TN; j++)
                    acc[i][j] += ar[i] * br[j];
        }
        __syncthreads();
    }

    #pragma unroll
    for (int i = 0; i < TM; i++) {
        size_t r = (size_t)(row0 + ty * TM + i);
        float*       Crow = C   + r * N;
        const float* Rrow = RES ? res + r * N : nullptr;
        #pragma unroll
        for (int j = 0; j < TN; j++) {
            int c = col0 + tx * TN + j;
            float v = acc[i][j];
            if (BIAS) v += bias[c];
            if (RES)  v += Rrow[c];
            if (RELU) v = fmaxf(v, 0.f);
            Crow[c] = v;
        }
    }
}

// ---------------------------------------------------------------------------
// Causal attention, one block per (query row, b*h). 128 threads.
// qkv layout: row bt = b*SEQ+t, cols [0,1024)=Q, [1024,2048)=K, [2048,3072)=V,
// head h occupies cols h*64..h*64+63 of each third.
// scale = 1/sqrt(D_MODEL) = 1/32 (reference uses emb_dim scaling).
// ---------------------------------------------------------------------------
__global__ __launch_bounds__(128)
void attn_kernel()
{
    int tq = blockIdx.x;
    int bh = blockIdx.y;
    int b  = bh >> 4;
    int h  = bh & 15;
    int tid = threadIdx.x;

    __shared__ float sq[HDIM];
    __shared__ float sc[SEQ];
    __shared__ float red[128];

    const float* qrow  = g_qkv + ((size_t)(b*SEQ + tq)) * (3*D_MODEL) + h*HDIM;
    const float* kbase = g_qkv + (size_t)b*SEQ*(3*D_MODEL) + D_MODEL   + h*HDIM;
    const float* vbase = g_qkv + (size_t)b*SEQ*(3*D_MODEL) + 2*D_MODEL + h*HDIM;

    if (tid < HDIM) sq[tid] = qrow[tid];
    __syncthreads();

    const float scale = 0.03125f;  // 1/sqrt(1024)
    float lmax = -3.4e38f;
    for (int s = tid; s <= tq; s += 128) {
        const float4* k4 = (const float4*)(kbase + (size_t)s * (3*D_MODEL));
        const float4* q4 = (const float4*)sq;
        float acc = 0.f;
        #pragma unroll
        for (int i = 0; i < HDIM/4; i++) {
            float4 kv = k4[i], qv = q4[i];
            acc += kv.x*qv.x + kv.y*qv.y + kv.z*qv.z + kv.w*qv.w;
        }
        acc *= scale;
        sc[s] = acc;
        lmax = fmaxf(lmax, acc);
    }

    // block max
    red[tid] = lmax; __syncthreads();
    for (int st = 64; st > 0; st >>= 1) {
        if (tid < st) red[tid] = fmaxf(red[tid], red[tid + st]);
        __syncthreads();
    }
    float m = red[0];
    __syncthreads();

    // exp + block sum
    float lsum = 0.f;
    for (int s = tid; s <= tq; s += 128) {
        float p = __expf(sc[s] - m);
        sc[s] = p;
        lsum += p;
    }
    red[tid] = lsum; __syncthreads();
    for (int st = 64; st > 0; st >>= 1) {
        if (tid < st) red[tid] += red[tid + st];
        __syncthreads();
    }
    float inv = 1.f / red[0];
    __syncthreads();

    // O = P * V  (2 threads per output dim, split over even/odd s)
    int e = tid & 63, half = tid >> 6;
    float acc = 0.f;
    for (int s = half; s <= tq; s += 2)
        acc += sc[s] * vbase[(size_t)s * (3*D_MODEL) + e];
    red[tid] = acc; __syncthreads();
    if (tid < HDIM)
        g_o[((size_t)(b*SEQ + tq)) * D_MODEL + h*HDIM + e] =
            (red[tid] + red[tid + 64]) * inv;
}

// ---------------------------------------------------------------------------
// Launch
// ---------------------------------------------------------------------------
static inline dim3 ggrid(int M, int N) { return dim3(N / BN, M / BM); }

extern "C" void kernel_launch(void* const* d_in, const int* in_sizes, int n_in,
                              void* d_out, int out_size)
{
    const int*   x      = (const int*)  d_in[0];
    const float* tok    = (const float*)d_in[1];
    const float* pos    = (const float*)d_in[2];
    const float* Wq     = (const float*)d_in[3];
    const float* Wk     = (const float*)d_in[4];
    const float* Wv     = (const float*)d_in[5];
    const float* Wproj  = (const float*)d_in[6];
    const float* bproj  = (const float*)d_in[7];
    const float* ln1_g  = (const float*)d_in[8];
    const float* ln1_b  = (const float*)d_in[9];
    const float* ln2_g  = (const float*)d_in[10];
    const float* ln2_b  = (const float*)d_in[11];
    const float* W1     = (const float*)d_in[12];
    const float* b1     = (const float*)d_in[13];
    const float* W2     = (const float*)d_in[14];
    const float* b2     = (const float*)d_in[15];
    const float* lnf_g  = (const float*)d_in[16];
    const float* lnf_b  = (const float*)d_in[17];
    const float* Wlm    = (const float*)d_in[18];
    const float* blm    = (const float*)d_in[19];
    float* out = (float*)d_out;

    float *h_, *ln_, *qkv_, *o_, *f_, *wq_;
    cudaGetSymbolAddress((void**)&h_,   g_h);
    cudaGetSymbolAddress((void**)&ln_,  g_ln);
    cudaGetSymbolAddress((void**)&qkv_, g_qkv);
    cudaGetSymbolAddress((void**)&o_,   g_o);
    cudaGetSymbolAddress((void**)&f_,   g_f);
    cudaGetSymbolAddress((void**)&wq_,  g_wqkv);

    // repack QKV weights: 8*3*16*1024*64 = 25,165,824 elems
    {
        size_t n = (size_t)NLAYER * 3 * NHEAD * D_MODEL * HDIM;
        repack_kernel<<<(unsigned)(n / 256), 256>>>(Wq, Wk, Wv);
    }

    // embeddings
    embed_kernel<<<(BT * D_MODEL) / 256, 256>>>(x, tok, pos);

    for (int l = 0; l < NLAYER; l++) {
        // a_in = LN1(h)
        ln_kernel<<<BT, 256>>>(h_, ln1_g + (size_t)l*D_MODEL, ln1_b + (size_t)l*D_MODEL, ln_);
        // qkv = a_in @ Wqkv_packed
        sgemm<false, false, false><<<ggrid(BT, 3*D_MODEL), 256>>>(
            ln_, wq_ + (size_t)l*D_MODEL*3*D_MODEL, nullptr, nullptr, qkv_,
            BT, 3*D_MODEL, D_MODEL);
        // attention
        attn_kernel<<<dim3(SEQ, BATCH*NHEAD), 128>>>();
        // h = h + o @ Wproj + bproj
        sgemm<true, false, true><<<ggrid(BT, D_MODEL), 256>>>(
            o_, Wproj + (size_t)l*D_MODEL*D_MODEL, bproj + (size_t)l*D_MODEL, h_, h_,
            BT, D_MODEL, D_MODEL);
        // f_in = LN2(h)
        ln_kernel<<<BT, 256>>>(h_, ln2_g + (size_t)l*D_MODEL, ln2_b + (size_t)l*D_MODEL, ln_);
        // f = relu(f_in @ W1 + b1)
        sgemm<true, true, false><<<ggrid(BT, DFF), 256>>>(
            ln_, W1 + (size_t)l*D_MODEL*DFF, b1 + (size_t)l*DFF, nullptr, f_,
            BT, DFF, D_MODEL);
        // h = h + f @ W2 + b2
        sgemm<true, false, true><<<ggrid(BT, D_MODEL), 256>>>(
            f_, W2 + (size_t)l*DFF*D_MODEL, b2 + (size_t)l*D_MODEL, h_, h_,
            BT, D_MODEL, DFF);
    }

    // final LN + LM head
    ln_kernel<<<BT, 256>>>(h_, lnf_g, lnf_b, ln_);
    sgemm<true, false, false><<<ggrid(BT, VOCAB), 256>>>(
        ln_, Wlm, blm, nullptr, out, BT, VOCAB, D_MODEL);
}

// round 6
// speedup vs baseline: 5.6336x; 5.6336x over previous
#include <cuda_runtime.h>
#include <cuda_bf16.h>
#include <cstdint>
#include <math.h>

#define D_MODEL 1024
#define NHEAD 16
#define HDIM 64
#define SEQ 1024
#define NLAYER 8
#define BATCH 2
#define BT (BATCH*SEQ)
#define DFF 4096
#define VOCAB 32000

// ---------------- helpers ----------------
__device__ __forceinline__ uint32_t smem_to_u32(const void* p) {
    uint32_t a;
    asm("{ .reg .u64 t; cvta.to.shared.u64 t, %1; cvt.u32.u64 %0, t; }":"=r"(a):"l"(p));
    return a;
}
__device__ __forceinline__ void ldsm4(uint32_t* r, uint32_t a) {
    asm volatile("ldmatrix.sync.aligned.m8n8.x4.shared.b16 {%0,%1,%2,%3}, [%4];"
        :"=r"(r[0]),"=r"(r[1]),"=r"(r[2]),"=r"(r[3]):"r"(a));
}
__device__ __forceinline__ void ldsm2(uint32_t* r, uint32_t a) {
    asm volatile("ldmatrix.sync.aligned.m8n8.x2.shared.b16 {%0,%1}, [%2];"
        :"=r"(r[0]),"=r"(r[1]):"r"(a));
}
#define MMA16816(c, a, b) asm volatile( \
    "mma.sync.aligned.m16n8k16.row.col.f32.bf16.bf16.f32 " \
    "{%0,%1,%2,%3}, {%4,%5,%6,%7}, {%8,%9}, {%0,%1,%2,%3};" \
    : "+f"((c)[0]),"+f"((c)[1]),"+f"((c)[2]),"+f"((c)[3]) \
    : "r"((a)[0]),"r"((a)[1]),"r"((a)[2]),"r"((a)[3]),"r"((b)[0]),"r"((b)[1]))

__device__ __forceinline__ uint32_t b2u(__nv_bfloat16 a, __nv_bfloat16 b) {
    __nv_bfloat162 t(a, b);
    return *reinterpret_cast<uint32_t*>(&t);
}
__device__ __forceinline__ void split2(float a, float b, uint32_t& hi, uint32_t& lo) {
    __nv_bfloat16 ha=__float2bfloat16(a), hb=__float2bfloat16(b);
    __nv_bfloat16 la=__float2bfloat16(a-__bfloat162float(ha));
    __nv_bfloat16 lb=__float2bfloat16(b-__bfloat162float(hb));
    hi=b2u(ha,hb); lo=b2u(la,lb);
}

// ---------------- scratch ----------------
__device__ float g_h  [(size_t)BT*D_MODEL];
__device__ float g_ln [(size_t)BT*D_MODEL];
__device__ float g_qkv[(size_t)BT*3*D_MODEL];
__device__ float g_o  [(size_t)BT*D_MODEL];
__device__ float g_f  [(size_t)BT*DFF];
__device__ __nv_bfloat16 g_qT_h[(size_t)NLAYER*3*D_MODEL*D_MODEL];
__device__ __nv_bfloat16 g_qT_l[(size_t)NLAYER*3*D_MODEL*D_MODEL];
__device__ __nv_bfloat16 g_pT_h[(size_t)NLAYER*D_MODEL*D_MODEL];
__device__ __nv_bfloat16 g_pT_l[(size_t)NLAYER*D_MODEL*D_MODEL];
__device__ __nv_bfloat16 g_w1h[(size_t)NLAYER*DFF*D_MODEL];
__device__ __nv_bfloat16 g_w1l[(size_t)NLAYER*DFF*D_MODEL];
__device__ __nv_bfloat16 g_w2h[(size_t)NLAYER*D_MODEL*DFF];
__device__ __nv_bfloat16 g_w2l[(size_t)NLAYER*D_MODEL*DFF];
__device__ __nv_bfloat16 g_lmh[(size_t)VOCAB*D_MODEL];
__device__ __nv_bfloat16 g_lml[(size_t)VOCAB*D_MODEL];

// ---------------- weight prep ----------------
// src [K,N] fp32 -> dh/dl [N][K] bf16 hi/lo
__global__ void transpose_split(const float* __restrict__ src, __nv_bfloat16* __restrict__ dh,
                                __nv_bfloat16* __restrict__ dl, int K, int N,
                                size_t sStr, size_t dStr)
{
    __shared__ float t[32][33];
    int b = blockIdx.z;
    src += (size_t)b*sStr; dh += (size_t)b*dStr; dl += (size_t)b*dStr;
    int n0 = blockIdx.x*32, k0 = blockIdx.y*32;
    #pragma unroll
    for (int i = threadIdx.y; i < 32; i += 8)
        t[i][threadIdx.x] = src[(size_t)(k0+i)*N + n0 + threadIdx.x];
    __syncthreads();
    #pragma unroll
    for (int i = threadIdx.y; i < 32; i += 8) {
        float v = t[threadIdx.x][i];
        __nv_bfloat16 h = __float2bfloat16(v);
        __nv_bfloat16 l = __float2bfloat16(v - __bfloat162float(h));
        size_t o = (size_t)(n0+i)*K + k0 + threadIdx.x;
        dh[o] = h; dl[o] = l;
    }
}

// Wq/Wk/Wv [L,H,D,HD] -> [L][3D(n)][D(k)]
__global__ void qkv_repack(const float* __restrict__ Wq, const float* __restrict__ Wk,
                           const float* __restrict__ Wv)
{
    __shared__ float t[32][33];
    int z = blockIdx.z;
    int h = z & 15, w = (z >> 4) % 3, l = z / 48;
    const float* src = ((w==0)?Wq:(w==1)?Wk:Wv) + ((size_t)(l*16+h))*D_MODEL*HDIM;
    size_t ob = ((size_t)l*3*D_MODEL + (size_t)w*D_MODEL + h*HDIM) * D_MODEL;
    int n0 = blockIdx.x*32, k0 = blockIdx.y*32;
    #pragma unroll
    for (int i = threadIdx.y; i < 32; i += 8)
        t[i][threadIdx.x] = src[(size_t)(k0+i)*HDIM + n0 + threadIdx.x];
    __syncthreads();
    #pragma unroll
    for (int i = threadIdx.y; i < 32; i += 8) {
        float v = t[threadIdx.x][i];
        __nv_bfloat16 hh = __float2bfloat16(v);
        __nv_bfloat16 ll = __float2bfloat16(v - __bfloat162float(hh));
        size_t o = ob + (size_t)(n0+i)*D_MODEL + k0 + threadIdx.x;
        g_qT_h[o] = hh; g_qT_l[o] = ll;
    }
}

// ---------------- embed / layernorm ----------------
__global__ void embed_kernel(const int* __restrict__ x, const float* __restrict__ tok,
                             const float* __restrict__ pos)
{
    int i = blockIdx.x*256 + threadIdx.x;
    int d = i & (D_MODEL-1), bt = i >> 10, t = bt & (SEQ-1);
    g_h[i] = tok[(size_t)x[bt]*D_MODEL + d] + pos[(size_t)t*D_MODEL + d];
}

__global__ __launch_bounds__(256)
void ln_kernel(const float* __restrict__ x, const float* __restrict__ gw,
               const float* __restrict__ bw, float* __restrict__ y)
{
    int row = blockIdx.x, tid = threadIdx.x;
    float4 v = ((const float4*)(x + (size_t)row*D_MODEL))[tid];
    float s = v.x+v.y+v.z+v.w;
    float q = v.x*v.x+v.y*v.y+v.z*v.z+v.w*v.w;
    #pragma unroll
    for (int o = 16; o > 0; o >>= 1) {
        s += __shfl_xor_sync(0xffffffffu, s, o);
        q += __shfl_xor_sync(0xffffffffu, q, o);
    }
    __shared__ float ss[8], sq[8];
    if ((tid&31)==0) { ss[tid>>5]=s; sq[tid>>5]=q; }
    __syncthreads();
    float ts=0.f, tq=0.f;
    #pragma unroll
    for (int i=0;i<8;i++){ ts+=ss[i]; tq+=sq[i]; }
    float mu = ts*(1.f/D_MODEL);
    float rstd = rsqrtf(tq*(1.f/D_MODEL) - mu*mu + 1e-5f);
    float4 g4 = ((const float4*)gw)[tid];
    float4 b4 = ((const float4*)bw)[tid];
    float4 o4;
    o4.x=(v.x-mu)*rstd*g4.x+b4.x; o4.y=(v.y-mu)*rstd*g4.y+b4.y;
    o4.z=(v.z-mu)*rstd*g4.z+b4.z; o4.w=(v.w-mu)*rstd*g4.w+b4.w;
    ((float4*)(y + (size_t)row*D_MODEL))[tid] = o4;
}

// ---------------- mma.sync GEMM ----------------
// C[M,N] = (RES?res:0) + A@W + (BIAS?bias:0), opt ReLU. A fp32, W pre-split [N][K].
// Block 128x128, BK=32, 8 warps (2m x 4n), warp tile 64x32.
// smem per stage (bf16 elems, rows padded to 40): Ah @0, Al @5120, Bh @10240, Bl @15360.
// Stage stride 20480 elems (40960 B); double-buffered = 81920 B dynamic smem.
#define GSMEM 81920

template <bool BIAS, bool RELU, bool RES>
__global__ __launch_bounds__(256, 1)
void gemm_mma(const float* __restrict__ A, const __nv_bfloat16* __restrict__ Bh,
              const __nv_bfloat16* __restrict__ Bl, const float* __restrict__ bias,
              const float* __restrict__ res, float* __restrict__ C, int M, int N, int K)
{
    extern __shared__ __nv_bfloat16 smg[];
    const int tid = threadIdx.x, lane = tid & 31, wid = tid >> 5;
    const int wm = wid >> 2, wn = wid & 3;
    const int row0 = blockIdx.x*128, col0 = blockIdx.y*128;
    const uint32_t sb = smem_to_u32(smg);

    int arow[4], akc[4];
    #pragma unroll
    for (int i=0;i<4;i++){ int ch = tid + i*256; arow[i]=ch>>3; akc[i]=ch&7; }
    int brow[2], bcc[2];
    #pragma unroll
    for (int i=0;i<2;i++){ int ch = tid + i*256; brow[i]=ch>>2; bcc[i]=ch&3; }

    float4 aR[4]; uint4 bhR[2], blR[2];
    float acc[4][4][4] = {};

    const uint32_t aLOff = (uint32_t)(((lane&7)+(lane&8))*80 + ((lane>>4)&1)*16);
    const int lb = lane & 15;
    const uint32_t bLOff = (uint32_t)((lb&7)*80 + ((lb>>3)&1)*16);
    const int nc = K/32;

    auto LOADG = [&](int c) {
        int k0 = c*32;
        #pragma unroll
        for (int i=0;i<4;i++)
            aR[i] = *(const float4*)(A + (size_t)(row0+arow[i])*K + k0 + akc[i]*4);
        #pragma unroll
        for (int i=0;i<2;i++){
            size_t o = (size_t)(col0+brow[i])*K + k0 + bcc[i]*8;
            bhR[i] = *(const uint4*)(Bh+o);
            blR[i] = *(const uint4*)(Bl+o);
        }
    };
    auto STORES = [&](int s) {
        __nv_bfloat16* bp = smg + s*20480;
        #pragma unroll
        for (int i=0;i<4;i++){
            uint32_t h0,l0,h1,l1;
            split2(aR[i].x,aR[i].y,h0,l0);
            split2(aR[i].z,aR[i].w,h1,l1);
            int off = arow[i]*40 + akc[i]*4;
            *(uint2*)(bp+off)      = make_uint2(h0,h1);
            *(uint2*)(bp+5120+off) = make_uint2(l0,l1);
        }
        #pragma unroll
        for (int i=0;i<2;i++){
            int off = brow[i]*40 + bcc[i]*8;
            *(uint4*)(bp+10240+off) = bhR[i];
            *(uint4*)(bp+15360+off) = blR[i];
        }
    };
    auto COMPUTE = [&](int s) {
        uint32_t base = sb + (uint32_t)s*40960u;
        #pragma unroll
        for (int kk=0;kk<2;kk++){
            uint32_t ah[4][4], al[4][4], bhf[4][2], blf[4][2];
            #pragma unroll
            for (int mt=0;mt<4;mt++){
                uint32_t ad = base + (uint32_t)((wm*64+mt*16)*80 + kk*32) + aLOff;
                ldsm4(ah[mt], ad);
                ldsm4(al[mt], ad + 10240u);
            }
            #pragma unroll
            for (int nt=0;nt<4;nt++){
                uint32_t bd = base + 20480u + (uint32_t)((wn*32+nt*8)*80 + kk*32) + bLOff;
                ldsm2(bhf[nt], bd);
                ldsm2(blf[nt], bd + 10240u);
            }
            #pragma unroll
            for (int mt=0;mt<4;mt++)
                #pragma unroll
                for (int nt=0;nt<4;nt++){
                    MMA16816(acc[mt][nt], ah[mt], bhf[nt]);
                    MMA16816(acc[mt][nt], ah[mt], blf[nt]);
                    MMA16816(acc[mt][nt], al[mt], bhf[nt]);
                }
        }
    };

    LOADG(0); STORES(0); __syncthreads();
    #pragma unroll 1
    for (int c = 0; c < nc; c++){
        if (c+1 < nc) LOADG(c+1);
        COMPUTE(c&1);
        if (c+1 < nc){ STORES((c+1)&1); __syncthreads(); }
    }

    #pragma unroll
    for (int mt=0;mt<4;mt++){
        int rg = row0 + wm*64 + mt*16 + (lane>>2);
        #pragma unroll
        for (int nt=0;nt<4;nt++){
            int cg = col0 + wn*32 + nt*8 + (lane&3)*2;
            float v0=acc[mt][nt][0], v1=acc[mt][nt][1];
            float v2=acc[mt][nt][2], v3=acc[mt][nt][3];
            if (BIAS){ float b0=bias[cg], b1=bias[cg+1]; v0+=b0; v1+=b1; v2+=b0; v3+=b1; }
            if (RES){
                float2 r0v = *(const float2*)(res+(size_t)rg*N+cg);
                float2 r1v = *(const float2*)(res+(size_t)(rg+8)*N+cg);
                v0+=r0v.x; v1+=r0v.y; v2+=r1v.x; v3+=r1v.y;
            }
            if (RELU){ v0=fmaxf(v0,0.f); v1=fmaxf(v1,0.f); v2=fmaxf(v2,0.f); v3=fmaxf(v3,0.f); }
            *(float2*)(C+(size_t)rg*N+cg)     = make_float2(v0,v1);
            *(float2*)(C+(size_t)(rg+8)*N+cg) = make_float2(v2,v3);
        }
    }
}

// ---------------- tiled causal attention ----------------
#define ASM_TOT ((4096*3 + 64*68 + 192)*4)
__global__ __launch_bounds__(256)
void attn2()
{
    extern __shared__ float a_[];
    float* Qs = a_;
    float* Ks = Qs + 4096;
    float* Vs = Ks + 4096;
    float* Ss = Vs + 4096;
    float* mA = Ss + 64*68;
    float* lA = mA + 64;
    float* sA = lA + 64;

    const int q0 = blockIdx.x*64, bh = blockIdx.y;
    const int b = bh >> 4, h = bh & 15;
    const int tid = threadIdx.x;
    const float* Qg = g_qkv + (size_t)b*SEQ*3072 + h*64;
    const float* Kg = Qg + 1024;
    const float* Vg = Qg + 2048;
    const int sRow = tid >> 2, sChk = (tid & 3)*16;

    #pragma unroll
    for (int eo = 0; eo < 16; eo += 4) {
        float4 v = *(const float4*)(Qg + (size_t)(q0+sRow)*3072 + sChk + eo);
        int e = sChk + eo;
        Qs[(e+0)*64+sRow]=v.x; Qs[(e+1)*64+sRow]=v.y; Qs[(e+2)*64+sRow]=v.z; Qs[(e+3)*64+sRow]=v.w;
    }
    if (tid < 64) { mA[tid] = -3e38f; lA[tid] = 0.f; }

    float o[4][4] = {};
    const int it = tid >> 4, jt = tid & 15;
    const int i0 = it*4, j0 = jt*4;
    __syncthreads();

    const int ntile = q0/64 + 1;
    for (int tI = 0; tI < ntile; tI++) {
        const int s0 = tI*64;
        #pragma unroll
        for (int eo = 0; eo < 16; eo += 4) {
            float4 kv = *(const float4*)(Kg + (size_t)(s0+sRow)*3072 + sChk + eo);
            int e = sChk + eo;
            Ks[(e+0)*64+sRow]=kv.x; Ks[(e+1)*64+sRow]=kv.y; Ks[(e+2)*64+sRow]=kv.z; Ks[(e+3)*64+sRow]=kv.w;
            float4 vv = *(const float4*)(Vg + (size_t)(s0+sRow)*3072 + sChk + eo);
            *(float4*)(Vs + sRow*64 + sChk + eo) = vv;
        }
        __syncthreads();

        float sa[4][4] = {};
        #pragma unroll 8
        for (int e = 0; e < 64; e++) {
            float4 qv = *(const float4*)(Qs + e*64 + i0);
            float4 kv = *(const float4*)(Ks + e*64 + j0);
            float qr[4] = {qv.x,qv.y,qv.z,qv.w};
            float kr[4] = {kv.x,kv.y,kv.z,kv.w};
            #pragma unroll
            for (int a = 0; a < 4; a++)
                #pragma unroll
                for (int c = 0; c < 4; c++) sa[a][c] += qr[a]*kr[c];
        }
        #pragma unroll
        for (int a = 0; a < 4; a++)
            #pragma unroll
            for (int c = 0; c < 4; c++) {
                float v = sa[a][c]*0.03125f;
                if (s0+j0+c > q0+i0+a) v = -3e38f;
                Ss[(i0+a)*68 + j0+c] = v;
            }
        __syncthreads();

        if (tid < 64) {
            float mo = mA[tid], mx = mo;
            #pragma unroll 8
            for (int j = 0; j < 64; j++) mx = fmaxf(mx, Ss[tid*68+j]);
            float sc = __expf(mo - mx), ls = 0.f;
            #pragma unroll 8
            for (int j = 0; j < 64; j++) {
                float p = __expf(Ss[tid*68+j] - mx);
                Ss[tid*68+j] = p; ls += p;
            }
            mA[tid] = mx; sA[tid] = sc; lA[tid] = lA[tid]*sc + ls;
        }
        __syncthreads();

        #pragma unroll
        for (int a = 0; a < 4; a++) {
            float s = sA[i0+a];
            #pragma unroll
            for (int c = 0; c < 4; c++) o[a][c] *= s;
        }
        #pragma unroll 8
        for (int s = 0; s < 64; s++) {
            float4 vv = *(const float4*)(Vs + s*64 + j0);
            float vr[4] = {vv.x,vv.y,vv.z,vv.w};
            float p0 = Ss[(i0+0)*68+s], p1 = Ss[(i0+1)*68+s];
            float p2 = Ss[(i0+2)*68+s], p3 = Ss[(i0+3)*68+s];
            #pragma unroll
            for (int c = 0; c < 4; c++) {
                o[0][c]+=p0*vr[c]; o[1][c]+=p1*vr[c]; o[2][c]+=p2*vr[c]; o[3][c]+=p3*vr[c];
            }
        }
        __syncthreads();
    }
    #pragma unroll
    for (int a = 0; a < 4; a++) {
        float inv = 1.f / lA[i0+a];
        float4 v = make_float4(o[a][0]*inv, o[a][1]*inv, o[a][2]*inv, o[a][3]*inv);
        *(float4*)(g_o + (size_t)(b*SEQ + q0 + i0 + a)*D_MODEL + h*64 + j0) = v;
    }
}

// ---------------- launch ----------------
extern "C" void kernel_launch(void* const* d_in, const int* in_sizes, int n_in,
                              void* d_out, int out_size)
{
    const int*   x     = (const int*)  d_in[0];
    const float* tok   = (const float*)d_in[1];
    const float* pos   = (const float*)d_in[2];
    const float* Wq    = (const float*)d_in[3];
    const float* Wk    = (const float*)d_in[4];
    const float* Wv    = (const float*)d_in[5];
    const float* Wproj = (const float*)d_in[6];
    const float* bproj = (const float*)d_in[7];
    const float* ln1_g = (const float*)d_in[8];
    const float* ln1_b = (const float*)d_in[9];
    const float* ln2_g = (const float*)d_in[10];
    const float* ln2_b = (const float*)d_in[11];
    const float* W1    = (const float*)d_in[12];
    const float* b1    = (const float*)d_in[13];
    const float* W2    = (const float*)d_in[14];
    const float* b2    = (const float*)d_in[15];
    const float* lnf_g = (const float*)d_in[16];
    const float* lnf_b = (const float*)d_in[17];
    const float* Wlm   = (const float*)d_in[18];
    const float* blm   = (const float*)d_in[19];
    float* out = (float*)d_out;

    float *h_, *ln_, *qkv_, *o_, *f_;
    __nv_bfloat16 *qTh,*qTl,*pTh,*pTl,*w1h,*w1l,*w2h,*w2l,*lmh,*lml;
    cudaGetSymbolAddress((void**)&h_,  g_h);
    cudaGetSymbolAddress((void**)&ln_, g_ln);
    cudaGetSymbolAddress((void**)&qkv_,g_qkv);
    cudaGetSymbolAddress((void**)&o_,  g_o);
    cudaGetSymbolAddress((void**)&f_,  g_f);
    cudaGetSymbolAddress((void**)&qTh, g_qT_h);
    cudaGetSymbolAddress((void**)&qTl, g_qT_l);
    cudaGetSymbolAddress((void**)&pTh, g_pT_h);
    cudaGetSymbolAddress((void**)&pTl, g_pT_l);
    cudaGetSymbolAddress((void**)&w1h, g_w1h);
    cudaGetSymbolAddress((void**)&w1l, g_w1l);
    cudaGetSymbolAddress((void**)&w2h, g_w2h);
    cudaGetSymbolAddress((void**)&w2l, g_w2l);
    cudaGetSymbolAddress((void**)&lmh, g_lmh);
    cudaGetSymbolAddress((void**)&lml, g_lml);

    cudaFuncSetAttribute(gemm_mma<false,false,false>, cudaFuncAttributeMaxDynamicSharedMemorySize, GSMEM);
    cudaFuncSetAttribute(gemm_mma<true,false,true>,   cudaFuncAttributeMaxDynamicSharedMemorySize, GSMEM);
    cudaFuncSetAttribute(gemm_mma<true,true,false>,   cudaFuncAttributeMaxDynamicSharedMemorySize, GSMEM);
    cudaFuncSetAttribute(gemm_mma<true,false,false>,  cudaFuncAttributeMaxDynamicSharedMemorySize, GSMEM);
    cudaFuncSetAttribute(attn2, cudaFuncAttributeMaxDynamicSharedMemorySize, ASM_TOT);

    dim3 tb(32, 8);
    qkv_repack<<<dim3(2, 32, NLAYER*48), tb>>>(Wq, Wk, Wv);
    transpose_split<<<dim3(32, 32, NLAYER), tb>>>(Wproj, pTh, pTl, D_MODEL, D_MODEL,
        (size_t)D_MODEL*D_MODEL, (size_t)D_MODEL*D_MODEL);
    transpose_split<<<dim3(128, 32, NLAYER), tb>>>(W1, w1h, w1l, D_MODEL, DFF,
        (size_t)D_MODEL*DFF, (size_t)D_MODEL*DFF);
    transpose_split<<<dim3(32, 128, NLAYER), tb>>>(W2, w2h, w2l, DFF, D_MODEL,
        (size_t)D_MODEL*DFF, (size_t)D_MODEL*DFF);
    transpose_split<<<dim3(1000, 32, 1), tb>>>(Wlm, lmh, lml, D_MODEL, VOCAB, 0, 0);

    embed_kernel<<<(BT*D_MODEL)/256, 256>>>(x, tok, pos);

    for (int l = 0; l < NLAYER; l++) {
        ln_kernel<<<BT, 256>>>(h_, ln1_g + (size_t)l*D_MODEL, ln1_b + (size_t)l*D_MODEL, ln_);
        gemm_mma<false,false,false><<<dim3(BT/128, 3*D_MODEL/128), 256, GSMEM>>>(
            ln_, qTh + (size_t)l*3*D_MODEL*D_MODEL, qTl + (size_t)l*3*D_MODEL*D_MODEL,
            nullptr, nullptr, qkv_, BT, 3*D_MODEL, D_MODEL);
        attn2<<<dim3(SEQ/64, BATCH*NHEAD), 256, ASM_TOT>>>();
        gemm_mma<true,false,true><<<dim3(BT/128, D_MODEL/128), 256, GSMEM>>>(
            o_, pTh + (size_t)l*D_MODEL*D_MODEL, pTl + (size_t)l*D_MODEL*D_MODEL,
            bproj + (size_t)l*D_MODEL, h_, h_, BT, D_MODEL, D_MODEL);
        ln_kernel<<<BT, 256>>>(h_, ln2_g + (size_t)l*D_MODEL, ln2_b + (size_t)l*D_MODEL, ln_);
        gemm_mma<true,true,false><<<dim3(BT/128, DFF/128), 256, GSMEM>>>(
            ln_, w1h + (size_t)l*D_MODEL*DFF, w1l + (size_t)l*D_MODEL*DFF,
            b1 + (size_t)l*DFF, nullptr, f_, BT, DFF, D_MODEL);
        gemm_mma<true,false,true><<<dim3(BT/128, D_MODEL/128), 256, GSMEM>>>(
            f_, w2h + (size_t)l*D_MODEL*DFF, w2l + (size_t)l*D_MODEL*DFF,
            b2 + (size_t)l*D_MODEL, h_, h_, BT, D_MODEL, DFF);
    }

    ln_kernel<<<BT, 256>>>(h_, lnf_g, lnf_b, ln_);
    gemm_mma<true,false,false><<<dim3(BT/128, VOCAB/128), 256, GSMEM>>>(
        ln_, lmh, lml, blm, nullptr, out, BT, VOCAB, D_MODEL);
}

// round 10
// speedup vs baseline: 5.7426x; 1.0194x over previous
#include <cuda_runtime.h>
#include <cuda_bf16.h>
#include <cstdint>
#include <math.h>

#define D_MODEL 1024
#define NHEAD 16
#define HDIM 64
#define SEQ 1024
#define NLAYER 8
#define BATCH 2
#define BT (BATCH*SEQ)
#define DFF 4096
#define VOCAB 32000

// ---------------- helpers ----------------
__device__ __forceinline__ uint32_t smem_to_u32(const void* p) {
    uint32_t a;
    asm("{ .reg .u64 t; cvta.to.shared.u64 t, %1; cvt.u32.u64 %0, t; }":"=r"(a):"l"(p));
    return a;
}
__device__ __forceinline__ void ldsm4(uint32_t* r, uint32_t a) {
    asm volatile("ldmatrix.sync.aligned.m8n8.x4.shared.b16 {%0,%1,%2,%3}, [%4];"
        :"=r"(r[0]),"=r"(r[1]),"=r"(r[2]),"=r"(r[3]):"r"(a));
}
__device__ __forceinline__ void ldsm2(uint32_t* r, uint32_t a) {
    asm volatile("ldmatrix.sync.aligned.m8n8.x2.shared.b16 {%0,%1}, [%2];"
        :"=r"(r[0]),"=r"(r[1]):"r"(a));
}
#define MMA16816(c, a, b) asm volatile( \
    "mma.sync.aligned.m16n8k16.row.col.f32.bf16.bf16.f32 " \
    "{%0,%1,%2,%3}, {%4,%5,%6,%7}, {%8,%9}, {%0,%1,%2,%3};" \
    : "+f"((c)[0]),"+f"((c)[1]),"+f"((c)[2]),"+f"((c)[3]) \
    : "r"((a)[0]),"r"((a)[1]),"r"((a)[2]),"r"((a)[3]),"r"((b)[0]),"r"((b)[1]))

#define CPASYNC16(sa, g) asm volatile("cp.async.cg.shared.global [%0], [%1], 16;"::"r"(sa),"l"(g):"memory")
#define CPCOMMIT() asm volatile("cp.async.commit_group;":::"memory")
#define CPWAIT0()  asm volatile("cp.async.wait_group 0;":::"memory")

__device__ __forceinline__ uint32_t b2u(__nv_bfloat16 a, __nv_bfloat16 b) {
    __nv_bfloat162 t(a, b);
    return *reinterpret_cast<uint32_t*>(&t);
}
__device__ __forceinline__ void split2(float a, float b, uint32_t& hi, uint32_t& lo) {
    __nv_bfloat16 ha=__float2bfloat16(a), hb=__float2bfloat16(b);
    __nv_bfloat16 la=__float2bfloat16(a-__bfloat162float(ha));
    __nv_bfloat16 lb=__float2bfloat16(b-__bfloat162float(hb));
    hi=b2u(ha,hb); lo=b2u(la,lb);
}

// ---------------- scratch ----------------
__device__ float g_h  [(size_t)BT*D_MODEL];
__device__ float g_ln [(size_t)BT*D_MODEL];
__device__ float g_qkv[(size_t)BT*3*D_MODEL];
__device__ float g_o  [(size_t)BT*D_MODEL];
__device__ float g_f  [(size_t)BT*DFF];
__device__ __nv_bfloat16 g_qT_h[(size_t)NLAYER*3*D_MODEL*D_MODEL];
__device__ __nv_bfloat16 g_qT_l[(size_t)NLAYER*3*D_MODEL*D_MODEL];
__device__ __nv_bfloat16 g_pT_h[(size_t)NLAYER*D_MODEL*D_MODEL];
__device__ __nv_bfloat16 g_pT_l[(size_t)NLAYER*D_MODEL*D_MODEL];
__device__ __nv_bfloat16 g_w1h[(size_t)NLAYER*DFF*D_MODEL];
__device__ __nv_bfloat16 g_w1l[(size_t)NLAYER*DFF*D_MODEL];
__device__ __nv_bfloat16 g_w2h[(size_t)NLAYER*D_MODEL*DFF];
__device__ __nv_bfloat16 g_w2l[(size_t)NLAYER*D_MODEL*DFF];
__device__ __nv_bfloat16 g_lmh[(size_t)VOCAB*D_MODEL];
__device__ __nv_bfloat16 g_lml[(size_t)VOCAB*D_MODEL];

// ---------------- weight prep ----------------
__global__ void transpose_split(const float* __restrict__ src, __nv_bfloat16* __restrict__ dh,
                                __nv_bfloat16* __restrict__ dl, int K, int N,
                                size_t sStr, size_t dStr)
{
    __shared__ float t[32][33];
    int b = blockIdx.z;
    src += (size_t)b*sStr; dh += (size_t)b*dStr; dl += (size_t)b*dStr;
    int n0 = blockIdx.x*32, k0 = blockIdx.y*32;
    #pragma unroll
    for (int i = threadIdx.y; i < 32; i += 8)
        t[i][threadIdx.x] = src[(size_t)(k0+i)*N + n0 + threadIdx.x];
    __syncthreads();
    #pragma unroll
    for (int i = threadIdx.y; i < 32; i += 8) {
        float v = t[threadIdx.x][i];
        __nv_bfloat16 h = __float2bfloat16(v);
        __nv_bfloat16 l = __float2bfloat16(v - __bfloat162float(h));
        size_t o = (size_t)(n0+i)*K + k0 + threadIdx.x;
        dh[o] = h; dl[o] = l;
    }
}

__global__ void qkv_repack(const float* __restrict__ Wq, const float* __restrict__ Wk,
                           const float* __restrict__ Wv)
{
    __shared__ float t[32][33];
    int z = blockIdx.z;
    int h = z & 15, w = (z >> 4) % 3, l = z / 48;
    const float* src = ((w==0)?Wq:(w==1)?Wk:Wv) + ((size_t)(l*16+h))*D_MODEL*HDIM;
    size_t ob = ((size_t)l*3*D_MODEL + (size_t)w*D_MODEL + h*HDIM) * D_MODEL;
    int n0 = blockIdx.x*32, k0 = blockIdx.y*32;
    #pragma unroll
    for (int i = threadIdx.y; i < 32; i += 8)
        t[i][threadIdx.x] = src[(size_t)(k0+i)*HDIM + n0 + threadIdx.x];
    __syncthreads();
    #pragma unroll
    for (int i = threadIdx.y; i < 32; i += 8) {
        float v = t[threadIdx.x][i];
        __nv_bfloat16 hh = __float2bfloat16(v);
        __nv_bfloat16 ll = __float2bfloat16(v - __bfloat162float(hh));
        size_t o = ob + (size_t)(n0+i)*D_MODEL + k0 + threadIdx.x;
        g_qT_h[o] = hh; g_qT_l[o] = ll;
    }
}

// ---------------- embed / layernorm ----------------
__global__ void embed_kernel(const int* __restrict__ x, const float* __restrict__ tok,
                             const float* __restrict__ pos)
{
    int i = blockIdx.x*256 + threadIdx.x;
    int d = i & (D_MODEL-1), bt = i >> 10, t = bt & (SEQ-1);
    g_h[i] = tok[(size_t)x[bt]*D_MODEL + d] + pos[(size_t)t*D_MODEL + d];
}

__global__ __launch_bounds__(256)
void ln_kernel(const float* __restrict__ x, const float* __restrict__ gw,
               const float* __restrict__ bw, float* __restrict__ y)
{
    int row = blockIdx.x, tid = threadIdx.x;
    float4 v = ((const float4*)(x + (size_t)row*D_MODEL))[tid];
    float s = v.x+v.y+v.z+v.w;
    float q = v.x*v.x+v.y*v.y+v.z*v.z+v.w*v.w;
    #pragma unroll
    for (int o = 16; o > 0; o >>= 1) {
        s += __shfl_xor_sync(0xffffffffu, s, o);
        q += __shfl_xor_sync(0xffffffffu, q, o);
    }
    __shared__ float ss[8], sq[8];
    if ((tid&31)==0) { ss[tid>>5]=s; sq[tid>>5]=q; }
    __syncthreads();
    float ts=0.f, tq=0.f;
    #pragma unroll
    for (int i=0;i<8;i++){ ts+=ss[i]; tq+=sq[i]; }
    float mu = ts*(1.f/D_MODEL);
    float rstd = rsqrtf(tq*(1.f/D_MODEL) - mu*mu + 1e-5f);
    float4 g4 = ((const float4*)gw)[tid];
    float4 b4 = ((const float4*)bw)[tid];
    float4 o4;
    o4.x=(v.x-mu)*rstd*g4.x+b4.x; o4.y=(v.y-mu)*rstd*g4.y+b4.y;
    o4.z=(v.z-mu)*rstd*g4.z+b4.z; o4.w=(v.w-mu)*rstd*g4.w+b4.w;
    ((float4*)(y + (size_t)row*D_MODEL))[tid] = o4;
}

// ---------------- mma.sync GEMM ----------------
// Block 128x128, BK=32, 8 warps (2m x 4n), warp tile 64x32, 2 CTAs/SM.
// smem stage (bytes): Ah@0 Al@10240 Bh@20480 Bl@30720, stride 40960. 2 stages.
// A: fp32 -> registers -> split -> smem.  B: pre-split bf16 via cp.async.
#define GSMEM 81920

template <bool BIAS, bool RELU, bool RES>
__global__ __launch_bounds__(256, 2)
void gemm_mma(const float* __restrict__ A, const __nv_bfloat16* __restrict__ Bh,
              const __nv_bfloat16* __restrict__ Bl, const float* __restrict__ bias,
              const float* __restrict__ res, float* __restrict__ C, int M, int N, int K)
{
    extern __shared__ __nv_bfloat16 smg[];
    const int tid = threadIdx.x, lane = tid & 31, wid = tid >> 5;
    const int wm = wid >> 2, wn = wid & 3;
    const int row0 = blockIdx.x*128, col0 = blockIdx.y*128;
    const uint32_t sb = smem_to_u32(smg);

    int arow[4], akc[4];
    #pragma unroll
    for (int i=0;i<4;i++){ int ch = tid + i*256; arow[i]=ch>>3; akc[i]=ch&7; }
    int brow[2], bcc[2];
    #pragma unroll
    for (int i=0;i<2;i++){ int ch = tid + i*256; brow[i]=ch>>2; bcc[i]=ch&3; }

    float4 aR[4];
    float acc[4][4][4] = {};

    const uint32_t aLOff = (uint32_t)(((lane&7)+(lane&8))*80 + ((lane>>4)&1)*16);
    const int lb = lane & 15;
    const uint32_t bLOff = (uint32_t)((lb&7)*80 + ((lb>>3)&1)*16);
    const int nc = K/32;

    auto LOADA = [&](int c) {
        int k0 = c*32;
        #pragma unroll
        for (int i=0;i<4;i++)
            aR[i] = *(const float4*)(A + (size_t)(row0+arow[i])*K + k0 + akc[i]*4);
    };
    auto CPB = [&](int c) {
        int k0 = c*32;
        uint32_t stb = sb + (uint32_t)(c&1)*40960u;
        #pragma unroll
        for (int i=0;i<2;i++){
            const __nv_bfloat16* gh = Bh + (size_t)(col0+brow[i])*K + k0 + bcc[i]*8;
            const __nv_bfloat16* gl = Bl + (size_t)(col0+brow[i])*K + k0 + bcc[i]*8;
            uint32_t off = (uint32_t)(brow[i]*40 + bcc[i]*8)*2u;
            CPASYNC16(stb + 20480u + off, gh);
            CPASYNC16(stb + 30720u + off, gl);
        }
        CPCOMMIT();
    };
    auto STOREA = [&](int s) {
        __nv_bfloat16* bp = smg + s*20480;
        #pragma unroll
        for (int i=0;i<4;i++){
            uint32_t h0,l0,h1,l1;
            split2(aR[i].x,aR[i].y,h0,l0);
            split2(aR[i].z,aR[i].w,h1,l1);
            int off = arow[i]*40 + akc[i]*4;
            *(uint2*)(bp+off)      = make_uint2(h0,h1);
            *(uint2*)(bp+5120+off) = make_uint2(l0,l1);
        }
    };
    auto COMPUTE = [&](int s) {
        uint32_t base = sb + (uint32_t)s*40960u;
        #pragma unroll
        for (int kk=0;kk<2;kk++){
            uint32_t ah[4][4], al[4][4];
            #pragma unroll
            for (int mt=0;mt<4;mt++){
                uint32_t ad = base + (uint32_t)((wm*64+mt*16)*80 + kk*32) + aLOff;
                ldsm4(ah[mt], ad);
                ldsm4(al[mt], ad + 10240u);
            }
            #pragma unroll
            for (int nt=0;nt<4;nt++){
                uint32_t bh2[2], bl2[2];
                uint32_t bd = base + 20480u + (uint32_t)((wn*32+nt*8)*80 + kk*32) + bLOff;
                ldsm2(bh2, bd);
                ldsm2(bl2, bd + 10240u);
                #pragma unroll
                for (int mt=0;mt<4;mt++){
                    MMA16816(acc[mt][nt], ah[mt], bh2);
                    MMA16816(acc[mt][nt], ah[mt], bl2);
                    MMA16816(acc[mt][nt], al[mt], bh2);
                }
            }
        }
    };

    LOADA(0); CPB(0); STOREA(0); CPWAIT0(); __syncthreads();
    #pragma unroll 1
    for (int c = 0; c < nc; c++){
        if (c+1 < nc){ LOADA(c+1); CPB(c+1); }
        COMPUTE(c&1);
        if (c+1 < nc){ STOREA((c+1)&1); CPWAIT0(); __syncthreads(); }
    }

    #pragma unroll
    for (int mt=0;mt<4;mt++){
        int rg = row0 + wm*64 + mt*16 + (lane>>2);
        #pragma unroll
        for (int nt=0;nt<4;nt++){
            int cg = col0 + wn*32 + nt*8 + (lane&3)*2;
            float v0=acc[mt][nt][0], v1=acc[mt][nt][1];
            float v2=acc[mt][nt][2], v3=acc[mt][nt][3];
            if (BIAS){ float b0=bias[cg], b1=bias[cg+1]; v0+=b0; v1+=b1; v2+=b0; v3+=b1; }
            if (RES){
                float2 r0v = *(const float2*)(res+(size_t)rg*N+cg);
                float2 r1v = *(const float2*)(res+(size_t)(rg+8)*N+cg);
                v0+=r0v.x; v1+=r0v.y; v2+=r1v.x; v3+=r1v.y;
            }
            if (RELU){ v0=fmaxf(v0,0.f); v1=fmaxf(v1,0.f); v2=fmaxf(v2,0.f); v3=fmaxf(v3,0.f); }
            *(float2*)(C+(size_t)rg*N+cg)     = make_float2(v0,v1);
            *(float2*)(C+(size_t)(rg+8)*N+cg) = make_float2(v2,v3);
        }
    }
}

// ---------------- tiled causal attention ----------------
#define ASM_TOT ((4096*3 + 64*68 + 192)*4)
__global__ __launch_bounds__(256)
void attn2()
{
    extern __shared__ float a_[];
    float* Qs = a_;
    float* Ks = Qs + 4096;
    float* Vs = Ks + 4096;
    float* Ss = Vs + 4096;
    float* mA = Ss + 64*68;
    float* lA = mA + 64;
    float* sA = lA + 64;

    const int q0 = blockIdx.x*64, bh = blockIdx.y;
    const int b = bh >> 4, h = bh & 15;
    const int tid = threadIdx.x;
    const float* Qg = g_qkv + (size_t)b*SEQ*3072 + h*64;
    const float* Kg = Qg + 1024;
    const float* Vg = Qg + 2048;
    const int sRow = tid >> 2, sChk = (tid & 3)*16;

    #pragma unroll
    for (int eo = 0; eo < 16; eo += 4) {
        float4 v = *(const float4*)(Qg + (size_t)(q0+sRow)*3072 + sChk + eo);
        int e = sChk + eo;
        Qs[(e+0)*64+sRow]=v.x; Qs[(e+1)*64+sRow]=v.y; Qs[(e+2)*64+sRow]=v.z; Qs[(e+3)*64+sRow]=v.w;
    }
    if (tid < 64) { mA[tid] = -3e38f; lA[tid] = 0.f; }

    float o[4][4] = {};
    const int it = tid >> 4, jt = tid & 15;
    const int i0 = it*4, j0 = jt*4;
    __syncthreads();

    const int ntile = q0/64 + 1;
    for (int tI = 0; tI < ntile; tI++) {
        const int s0 = tI*64;
        #pragma unroll
        for (int eo = 0; eo < 16; eo += 4) {
            float4 kv = *(const float4*)(Kg + (size_t)(s0+sRow)*3072 + sChk + eo);
            int e = sChk + eo;
            Ks[(e+0)*64+sRow]=kv.x; Ks[(e+1)*64+sRow]=kv.y; Ks[(e+2)*64+sRow]=kv.z; Ks[(e+3)*64+sRow]=kv.w;
            float4 vv = *(const float4*)(Vg + (size_t)(s0+sRow)*3072 + sChk + eo);
            *(float4*)(Vs + sRow*64 + sChk + eo) = vv;
        }
        __syncthreads();

        float sa[4][4] = {};
        #pragma unroll 8
        for (int e = 0; e < 64; e++) {
            float4 qv = *(const float4*)(Qs + e*64 + i0);
            float4 kv = *(const float4*)(Ks + e*64 + j0);
            float qr[4] = {qv.x,qv.y,qv.z,qv.w};
            float kr[4] = {kv.x,kv.y,kv.z,kv.w};
            #pragma unroll
            for (int a = 0; a < 4; a++)
                #pragma unroll
                for (int c = 0; c < 4; c++) sa[a][c] += qr[a]*kr[c];
        }
        #pragma unroll
        for (int a = 0; a < 4; a++)
            #pragma unroll
            for (int c = 0; c < 4; c++) {
                float v = sa[a][c]*0.03125f;
                if (s0+j0+c > q0+i0+a) v = -3e38f;
                Ss[(i0+a)*68 + j0+c] = v;
            }
        __syncthreads();

        // online softmax: 4 threads per row
        {
            int r = tid >> 2, q4 = tid & 3;
            float mo = mA[r], mx = mo;
            #pragma unroll
            for (int j = q4*16; j < q4*16+16; j++) mx = fmaxf(mx, Ss[r*68+j]);
            mx = fmaxf(mx, __shfl_xor_sync(0xffffffffu, mx, 1));
            mx = fmaxf(mx, __shfl_xor_sync(0xffffffffu, mx, 2));
            float ls = 0.f;
            #pragma unroll
            for (int j = q4*16; j < q4*16+16; j++) {
                float p = __expf(Ss[r*68+j] - mx);
                Ss[r*68+j] = p; ls += p;
            }
            ls += __shfl_xor_sync(0xffffffffu, ls, 1);
            ls += __shfl_xor_sync(0xffffffffu, ls, 2);
            if (q4 == 0) {
                float sc = __expf(mo - mx);
                mA[r] = mx; sA[r] = sc; lA[r] = lA[r]*sc + ls;
            }
        }
        __syncthreads();

        #pragma unroll
        for (int a = 0; a < 4; a++) {
            float s = sA[i0+a];
            #pragma unroll
            for (int c = 0; c < 4; c++) o[a][c] *= s;
        }
        #pragma unroll 8
        for (int s = 0; s < 64; s++) {
            float4 vv = *(const float4*)(Vs + s*64 + j0);
            float vr[4] = {vv.x,vv.y,vv.z,vv.w};
            float p0 = Ss[(i0+0)*68+s], p1 = Ss[(i0+1)*68+s];
            float p2 = Ss[(i0+2)*68+s], p3 = Ss[(i0+3)*68+s];
            #pragma unroll
            for (int c = 0; c < 4; c++) {
                o[0][c]+=p0*vr[c]; o[1][c]+=p1*vr[c]; o[2][c]+=p2*vr[c]; o[3][c]+=p3*vr[c];
            }
        }
        __syncthreads();
    }
    #pragma unroll
    for (int a = 0; a < 4; a++) {
        float inv = 1.f / lA[i0+a];
        float4 v = make_float4(o[a][0]*inv, o[a][1]*inv, o[a][2]*inv, o[a][3]*inv);
        *(float4*)(g_o + (size_t)(b*SEQ + q0 + i0 + a)*D_MODEL + h*64 + j0) = v;
    }
}

// ---------------- launch ----------------
extern "C" void kernel_launch(void* const* d_in, const int* in_sizes, int n_in,
                              void* d_out, int out_size)
{
    const int*   x     = (const int*)  d_in[0];
    const float* tok   = (const float*)d_in[1];
    const float* pos   = (const float*)d_in[2];
    const float* Wq    = (const float*)d_in[3];
    const float* Wk    = (const float*)d_in[4];
    const float* Wv    = (const float*)d_in[5];
    const float* Wproj = (const float*)d_in[6];
    const float* bproj = (const float*)d_in[7];
    const float* ln1_g = (const float*)d_in[8];
    const float* ln1_b = (const float*)d_in[9];
    const float* ln2_g = (const float*)d_in[10];
    const float* ln2_b = (const float*)d_in[11];
    const float* W1    = (const float*)d_in[12];
    const float* b1    = (const float*)d_in[13];
    const float* W2    = (const float*)d_in[14];
    const float* b2    = (const float*)d_in[15];
    const float* lnf_g = (const float*)d_in[16];
    const float* lnf_b = (const float*)d_in[17];
    const float* Wlm   = (const float*)d_in[18];
    const float* blm   = (const float*)d_in[19];
    float* out = (float*)d_out;

    float *h_, *ln_, *qkv_, *o_, *f_;
    __nv_bfloat16 *qTh,*qTl,*pTh,*pTl,*w1h,*w1l,*w2h,*w2l,*lmh,*lml;
    cudaGetSymbolAddress((void**)&h_,  g_h);
    cudaGetSymbolAddress((void**)&ln_, g_ln);
    cudaGetSymbolAddress((void**)&qkv_,g_qkv);
    cudaGetSymbolAddress((void**)&o_,  g_o);
    cudaGetSymbolAddress((void**)&f_,  g_f);
    cudaGetSymbolAddress((void**)&qTh, g_qT_h);
    cudaGetSymbolAddress((void**)&qTl, g_qT_l);
    cudaGetSymbolAddress((void**)&pTh, g_pT_h);
    cudaGetSymbolAddress((void**)&pTl, g_pT_l);
    cudaGetSymbolAddress((void**)&w1h, g_w1h);
    cudaGetSymbolAddress((void**)&w1l, g_w1l);
    cudaGetSymbolAddress((void**)&w2h, g_w2h);
    cudaGetSymbolAddress((void**)&w2l, g_w2l);
    cudaGetSymbolAddress((void**)&lmh, g_lmh);
    cudaGetSymbolAddress((void**)&lml, g_lml);

    cudaFuncSetAttribute(gemm_mma<false,false,false>, cudaFuncAttributeMaxDynamicSharedMemorySize, GSMEM);
    cudaFuncSetAttribute(gemm_mma<true,false,true>,   cudaFuncAttributeMaxDynamicSharedMemorySize, GSMEM);
    cudaFuncSetAttribute(gemm_mma<true,true,false>,   cudaFuncAttributeMaxDynamicSharedMemorySize, GSMEM);
    cudaFuncSetAttribute(gemm_mma<true,false,false>,  cudaFuncAttributeMaxDynamicSharedMemorySize, GSMEM);
    cudaFuncSetAttribute(attn2, cudaFuncAttributeMaxDynamicSharedMemorySize, ASM_TOT);

    dim3 tb(32, 8);
    qkv_repack<<<dim3(2, 32, NLAYER*48), tb>>>(Wq, Wk, Wv);
    transpose_split<<<dim3(32, 32, NLAYER), tb>>>(Wproj, pTh, pTl, D_MODEL, D_MODEL,
        (size_t)D_MODEL*D_MODEL, (size_t)D_MODEL*D_MODEL);
    transpose_split<<<dim3(128, 32, NLAYER), tb>>>(W1, w1h, w1l, D_MODEL, DFF,
        (size_t)D_MODEL*DFF, (size_t)D_MODEL*DFF);
    transpose_split<<<dim3(32, 128, NLAYER), tb>>>(W2, w2h, w2l, DFF, D_MODEL,
        (size_t)D_MODEL*DFF, (size_t)D_MODEL*DFF);
    transpose_split<<<dim3(1000, 32, 1), tb>>>(Wlm, lmh, lml, D_MODEL, VOCAB, 0, 0);

    embed_kernel<<<(BT*D_MODEL)/256, 256>>>(x, tok, pos);

    for (int l = 0; l < NLAYER; l++) {
        ln_kernel<<<BT, 256>>>(h_, ln1_g + (size_t)l*D_MODEL, ln1_b + (size_t)l*D_MODEL, ln_);
        gemm_mma<false,false,false><<<dim3(BT/128, 3*D_MODEL/128), 256, GSMEM>>>(
            ln_, qTh + (size_t)l*3*D_MODEL*D_MODEL, qTl + (size_t)l*3*D_MODEL*D_MODEL,
            nullptr, nullptr, qkv_, BT, 3*D_MODEL, D_MODEL);
        attn2<<<dim3(SEQ/64, BATCH*NHEAD), 256, ASM_TOT>>>();
        gemm_mma<true,false,true><<<dim3(BT/128, D_MODEL/128), 256, GSMEM>>>(
            o_, pTh + (size_t)l*D_MODEL*D_MODEL, pTl + (size_t)l*D_MODEL*D_MODEL,
            bproj + (size_t)l*D_MODEL, h_, h_, BT, D_MODEL, D_MODEL);
        ln_kernel<<<BT, 256>>>(h_, ln2_g + (size_t)l*D_MODEL, ln2_b + (size_t)l*D_MODEL, ln_);
        gemm_mma<true,true,false><<<dim3(BT/128, DFF/128), 256, GSMEM>>>(
            ln_, w1h + (size_t)l*D_MODEL*DFF, w1l + (size_t)l*D_MODEL*DFF,
            b1 + (size_t)l*DFF, nullptr, f_, BT, DFF, D_MODEL);
        gemm_mma<true,false,true><<<dim3(BT/128, D_MODEL/128), 256, GSMEM>>>(
            f_, w2h + (size_t)l*D_MODEL*DFF, w2l + (size_t)l*D_MODEL*DFF,
            b2 + (size_t)l*D_MODEL, h_, h_, BT, D_MODEL, DFF);
    }

    ln_kernel<<<BT, 256>>>(h_, lnf_g, lnf_b, ln_);
    gemm_mma<true,false,false><<<dim3(BT/128, VOCAB/128), 256, GSMEM>>>(
        ln_, lmh, lml, blm, nullptr, out, BT, VOCAB, D_MODEL);
}

// round 15
// speedup vs baseline: 8.8001x; 1.5324x over previous
#include <cuda_runtime.h>
#include <cuda_fp16.h>
#include <cstdint>
#include <math.h>

#define D_MODEL 1024
#define NHEAD 16
#define HDIM 64
#define SEQ 1024
#define NLAYER 8
#define BATCH 2
#define BT (BATCH*SEQ)
#define DFF 4096
#define VOCAB 32000

// ---------------- helpers ----------------
__device__ __forceinline__ uint32_t smem_to_u32(const void* p) {
    uint32_t a;
    asm("{ .reg .u64 t; cvta.to.shared.u64 t, %1; cvt.u32.u64 %0, t; }":"=r"(a):"l"(p));
    return a;
}
__device__ __forceinline__ void ldsm4(uint32_t* r, uint32_t a) {
    asm volatile("ldmatrix.sync.aligned.m8n8.x4.shared.b16 {%0,%1,%2,%3}, [%4];"
        :"=r"(r[0]),"=r"(r[1]),"=r"(r[2]),"=r"(r[3]):"r"(a));
}
__device__ __forceinline__ void ldsm2(uint32_t* r, uint32_t a) {
    asm volatile("ldmatrix.sync.aligned.m8n8.x2.shared.b16 {%0,%1}, [%2];"
        :"=r"(r[0]),"=r"(r[1]):"r"(a));
}
#define MMAF16(c, a, b) asm volatile( \
    "mma.sync.aligned.m16n8k16.row.col.f32.f16.f16.f32 " \
    "{%0,%1,%2,%3}, {%4,%5,%6,%7}, {%8,%9}, {%0,%1,%2,%3};" \
    : "+f"((c)[0]),"+f"((c)[1]),"+f"((c)[2]),"+f"((c)[3]) \
    : "r"((a)[0]),"r"((a)[1]),"r"((a)[2]),"r"((a)[3]),"r"((b)[0]),"r"((b)[1]))

#define CPASYNC16(sa, g) asm volatile("cp.async.cg.shared.global [%0], [%1], 16;"::"r"(sa),"l"(g):"memory")
#define CPCOMMIT() asm volatile("cp.async.commit_group;":::"memory")
#define CPWAIT0()  asm volatile("cp.async.wait_group 0;":::"memory")

__device__ __forceinline__ uint32_t h2u(__half2 h) { return *reinterpret_cast<uint32_t*>(&h); }

// ---------------- scratch ----------------
__device__ float g_h  [(size_t)BT*D_MODEL];
__device__ float g_ln [(size_t)BT*D_MODEL];
__device__ float g_qkv[(size_t)BT*3*D_MODEL];
__device__ float g_o  [(size_t)BT*D_MODEL];
__device__ float g_f  [(size_t)BT*DFF];
__device__ __half g_qT[(size_t)NLAYER*3*D_MODEL*D_MODEL];
__device__ __half g_pT[(size_t)NLAYER*D_MODEL*D_MODEL];
__device__ __half g_w1[(size_t)NLAYER*DFF*D_MODEL];
__device__ __half g_w2[(size_t)NLAYER*D_MODEL*DFF];
__device__ __half g_lm[(size_t)VOCAB*D_MODEL];

// ---------------- weight prep ----------------
// src [K,N] fp32 -> d [N][K] fp16
__global__ void transpose_cvt(const float* __restrict__ src, __half* __restrict__ d,
                              int K, int N, size_t sStr, size_t dStr)
{
    __shared__ float t[32][33];
    int b = blockIdx.z;
    src += (size_t)b*sStr; d += (size_t)b*dStr;
    int n0 = blockIdx.x*32, k0 = blockIdx.y*32;
    #pragma unroll
    for (int i = threadIdx.y; i < 32; i += 8)
        t[i][threadIdx.x] = src[(size_t)(k0+i)*N + n0 + threadIdx.x];
    __syncthreads();
    #pragma unroll
    for (int i = threadIdx.y; i < 32; i += 8)
        d[(size_t)(n0+i)*K + k0 + threadIdx.x] = __float2half_rn(t[threadIdx.x][i]);
}

// Wq/Wk/Wv [L,H,D,HD] -> [L][3D(n)][D(k)] fp16
__global__ void qkv_repack(const float* __restrict__ Wq, const float* __restrict__ Wk,
                           const float* __restrict__ Wv)
{
    __shared__ float t[32][33];
    int z = blockIdx.z;
    int h = z & 15, w = (z >> 4) % 3, l = z / 48;
    const float* src = ((w==0)?Wq:(w==1)?Wk:Wv) + ((size_t)(l*16+h))*D_MODEL*HDIM;
    size_t ob = ((size_t)l*3*D_MODEL + (size_t)w*D_MODEL + h*HDIM) * D_MODEL;
    int n0 = blockIdx.x*32, k0 = blockIdx.y*32;
    #pragma unroll
    for (int i = threadIdx.y; i < 32; i += 8)
        t[i][threadIdx.x] = src[(size_t)(k0+i)*HDIM + n0 + threadIdx.x];
    __syncthreads();
    #pragma unroll
    for (int i = threadIdx.y; i < 32; i += 8)
        g_qT[ob + (size_t)(n0+i)*D_MODEL + k0 + threadIdx.x] = __float2half_rn(t[threadIdx.x][i]);
}

// ---------------- embed / layernorm ----------------
__global__ void embed_kernel(const int* __restrict__ x, const float* __restrict__ tok,
                             const float* __restrict__ pos)
{
    int i = blockIdx.x*256 + threadIdx.x;
    int d = i & (D_MODEL-1), bt = i >> 10, t = bt & (SEQ-1);
    g_h[i] = tok[(size_t)x[bt]*D_MODEL + d] + pos[(size_t)t*D_MODEL + d];
}

__global__ __launch_bounds__(256)
void ln_kernel(const float* __restrict__ x, const float* __restrict__ gw,
               const float* __restrict__ bw, float* __restrict__ y)
{
    int row = blockIdx.x, tid = threadIdx.x;
    float4 v = ((const float4*)(x + (size_t)row*D_MODEL))[tid];
    float s = v.x+v.y+v.z+v.w;
    float q = v.x*v.x+v.y*v.y+v.z*v.z+v.w*v.w;
    #pragma unroll
    for (int o = 16; o > 0; o >>= 1) {
        s += __shfl_xor_sync(0xffffffffu, s, o);
        q += __shfl_xor_sync(0xffffffffu, q, o);
    }
    __shared__ float ss[8], sq[8];
    if ((tid&31)==0) { ss[tid>>5]=s; sq[tid>>5]=q; }
    __syncthreads();
    float ts=0.f, tq=0.f;
    #pragma unroll
    for (int i=0;i<8;i++){ ts+=ss[i]; tq+=sq[i]; }
    float mu = ts*(1.f/D_MODEL);
    float rstd = rsqrtf(tq*(1.f/D_MODEL) - mu*mu + 1e-5f);
    float4 g4 = ((const float4*)gw)[tid];
    float4 b4 = ((const float4*)bw)[tid];
    float4 o4;
    o4.x=(v.x-mu)*rstd*g4.x+b4.x; o4.y=(v.y-mu)*rstd*g4.y+b4.y;
    o4.z=(v.z-mu)*rstd*g4.z+b4.z; o4.w=(v.w-mu)*rstd*g4.w+b4.w;
    ((float4*)(y + (size_t)row*D_MODEL))[tid] = o4;
}

// ---------------- mma.sync fp16 GEMM (single term) ----------------
// Block 128x128, BK=32, 8 warps (2m x 4n), warp tile 64x32, 2 CTAs/SM.
// smem stage (bytes): A@0 (128 rows x 40 halfs = 10240B), B@10240 (same). stride 20480. 2 stages.
// A: fp32 -> regs -> fp16 -> smem.  B: pre-converted fp16 via cp.async.
#define GSMEM 40960

template <bool BIAS, bool RELU, bool RES>
__global__ __launch_bounds__(256, 2)
void gemm_mma(const float* __restrict__ A, const __half* __restrict__ B,
              const float* __restrict__ bias, const float* __restrict__ res,
              float* __restrict__ C, int M, int N, int K)
{
    extern __shared__ __half smg[];
    const int tid = threadIdx.x, lane = tid & 31, wid = tid >> 5;
    const int wm = wid >> 2, wn = wid & 3;
    const int row0 = blockIdx.x*128, col0 = blockIdx.y*128;
    const uint32_t sb = smem_to_u32(smg);

    int arow[4], akc[4];
    #pragma unroll
    for (int i=0;i<4;i++){ int ch = tid + i*256; arow[i]=ch>>3; akc[i]=ch&7; }
    int brow[2], bcc[2];
    #pragma unroll
    for (int i=0;i<2;i++){ int ch = tid + i*256; brow[i]=ch>>2; bcc[i]=ch&3; }

    float4 aR[4];
    float acc[4][4][4] = {};

    const uint32_t aLOff = (uint32_t)(((lane&7)+(lane&8))*80 + ((lane>>4)&1)*16);
    const int lb = lane & 15;
    const uint32_t bLOff = (uint32_t)((lb&7)*80 + ((lb>>3)&1)*16);
    const int nc = K/32;

    auto LOADA = [&](int c) {
        int k0 = c*32;
        #pragma unroll
        for (int i=0;i<4;i++)
            aR[i] = *(const float4*)(A + (size_t)(row0+arow[i])*K + k0 + akc[i]*4);
    };
    auto CPB = [&](int c) {
        int k0 = c*32;
        uint32_t stb = sb + (uint32_t)(c&1)*20480u + 10240u;
        #pragma unroll
        for (int i=0;i<2;i++){
            const __half* g = B + (size_t)(col0+brow[i])*K + k0 + bcc[i]*8;
            CPASYNC16(stb + (uint32_t)(brow[i]*40 + bcc[i]*8)*2u, g);
        }
        CPCOMMIT();
    };
    auto STOREA = [&](int s) {
        __half* bp = smg + s*10240;
        #pragma unroll
        for (int i=0;i<4;i++){
            uint32_t u0 = h2u(__floats2half2_rn(aR[i].x, aR[i].y));
            uint32_t u1 = h2u(__floats2half2_rn(aR[i].z, aR[i].w));
            *(uint2*)(bp + arow[i]*40 + akc[i]*4) = make_uint2(u0, u1);
        }
    };
    auto COMPUTE = [&](int s) {
        uint32_t base = sb + (uint32_t)s*20480u;
        #pragma unroll
        for (int kk=0;kk<2;kk++){
            uint32_t ah[4][4];
            #pragma unroll
            for (int mt=0;mt<4;mt++)
                ldsm4(ah[mt], base + (uint32_t)((wm*64+mt*16)*80 + kk*32) + aLOff);
            #pragma unroll
            for (int nt=0;nt<4;nt++){
                uint32_t b2[2];
                ldsm2(b2, base + 10240u + (uint32_t)((wn*32+nt*8)*80 + kk*32) + bLOff);
                #pragma unroll
                for (int mt=0;mt<4;mt++)
                    MMAF16(acc[mt][nt], ah[mt], b2);
            }
        }
    };

    LOADA(0); CPB(0); STOREA(0); CPWAIT0(); __syncthreads();
    #pragma unroll 1
    for (int c = 0; c < nc; c++){
        if (c+1 < nc){ LOADA(c+1); CPB(c+1); }
        COMPUTE(c&1);
        if (c+1 < nc){ STOREA((c+1)&1); CPWAIT0(); __syncthreads(); }
    }

    #pragma unroll
    for (int mt=0;mt<4;mt++){
        int rg = row0 + wm*64 + mt*16 + (lane>>2);
        #pragma unroll
        for (int nt=0;nt<4;nt++){
            int cg = col0 + wn*32 + nt*8 + (lane&3)*2;
            float v0=acc[mt][nt][0], v1=acc[mt][nt][1];
            float v2=acc[mt][nt][2], v3=acc[mt][nt][3];
            if (BIAS){ float b0=bias[cg], b1=bias[cg+1]; v0+=b0; v1+=b1; v2+=b0; v3+=b1; }
            if (RES){
                float2 r0v = *(const float2*)(res+(size_t)rg*N+cg);
                float2 r1v = *(const float2*)(res+(size_t)(rg+8)*N+cg);
                v0+=r0v.x; v1+=r0v.y; v2+=r1v.x; v3+=r1v.y;
            }
            if (RELU){ v0=fmaxf(v0,0.f); v1=fmaxf(v1,0.f); v2=fmaxf(v2,0.f); v3=fmaxf(v3,0.f); }
            *(float2*)(C+(size_t)rg*N+cg)     = make_float2(v0,v1);
            *(float2*)(C+(size_t)(rg+8)*N+cg) = make_float2(v2,v3);
        }
    }
}

// ---------------- tiled causal attention ----------------
#define ASM_TOT ((4096*3 + 64*68 + 192)*4)
__global__ __launch_bounds__(256)
void attn2()
{
    extern __shared__ float a_[];
    float* Qs = a_;
    float* Ks = Qs + 4096;
    float* Vs = Ks + 4096;
    float* Ss = Vs + 4096;
    float* mA = Ss + 64*68;
    float* lA = mA + 64;
    float* sA = lA + 64;

    const int q0 = blockIdx.x*64, bh = blockIdx.y;
    const int b = bh >> 4, h = bh & 15;
    const int tid = threadIdx.x;
    const float* Qg = g_qkv + (size_t)b*SEQ*3072 + h*64;
    const float* Kg = Qg + 1024;
    const float* Vg = Qg + 2048;
    const int sRow = tid >> 2, sChk = (tid & 3)*16;

    #pragma unroll
    for (int eo = 0; eo < 16; eo += 4) {
        float4 v = *(const float4*)(Qg + (size_t)(q0+sRow)*3072 + sChk + eo);
        int e = sChk + eo;
        Qs[(e+0)*64+sRow]=v.x; Qs[(e+1)*64+sRow]=v.y; Qs[(e+2)*64+sRow]=v.z; Qs[(e+3)*64+sRow]=v.w;
    }
    if (tid < 64) { mA[tid] = -3e38f; lA[tid] = 0.f; }

    float o[4][4] = {};
    const int it = tid >> 4, jt = tid & 15;
    const int i0 = it*4, j0 = jt*4;
    __syncthreads();

    const int ntile = q0/64 + 1;
    for (int tI = 0; tI < ntile; tI++) {
        const int s0 = tI*64;
        #pragma unroll
        for (int eo = 0; eo < 16; eo += 4) {
            float4 kv = *(const float4*)(Kg + (size_t)(s0+sRow)*3072 + sChk + eo);
            int e = sChk + eo;
            Ks[(e+0)*64+sRow]=kv.x; Ks[(e+1)*64+sRow]=kv.y; Ks[(e+2)*64+sRow]=kv.z; Ks[(e+3)*64+sRow]=kv.w;
            float4 vv = *(const float4*)(Vg + (size_t)(s0+sRow)*3072 + sChk + eo);
            *(float4*)(Vs + sRow*64 + sChk + eo) = vv;
        }
        __syncthreads();

        float sa[4][4] = {};
        #pragma unroll 8
        for (int e = 0; e < 64; e++) {
            float4 qv = *(const float4*)(Qs + e*64 + i0);
            float4 kv = *(const float4*)(Ks + e*64 + j0);
            float qr[4] = {qv.x,qv.y,qv.z,qv.w};
            float kr[4] = {kv.x,kv.y,kv.z,kv.w};
            #pragma unroll
            for (int a = 0; a < 4; a++)
                #pragma unroll
                for (int c = 0; c < 4; c++) sa[a][c] += qr[a]*kr[c];
        }
        #pragma unroll
        for (int a = 0; a < 4; a++)
            #pragma unroll
            for (int c = 0; c < 4; c++) {
                float v = sa[a][c]*0.03125f;
                if (s0+j0+c > q0+i0+a) v = -3e38f;
                Ss[(i0+a)*68 + j0+c] = v;
            }
        __syncthreads();

        // online softmax: 4 threads per row
        {
            int r = tid >> 2, q4 = tid & 3;
            float mo = mA[r], mx = mo;
            #pragma unroll
            for (int j = q4*16; j < q4*16+16; j++) mx = fmaxf(mx, Ss[r*68+j]);
            mx = fmaxf(mx, __shfl_xor_sync(0xffffffffu, mx, 1));
            mx = fmaxf(mx, __shfl_xor_sync(0xffffffffu, mx, 2));
            float ls = 0.f;
            #pragma unroll
            for (int j = q4*16; j < q4*16+16; j++) {
                float p = __expf(Ss[r*68+j] - mx);
                Ss[r*68+j] = p; ls += p;
            }
            ls += __shfl_xor_sync(0xffffffffu, ls, 1);
            ls += __shfl_xor_sync(0xffffffffu, ls, 2);
            if (q4 == 0) {
                float sc = __expf(mo - mx);
                mA[r] = mx; sA[r] = sc; lA[r] = lA[r]*sc + ls;
            }
        }
        __syncthreads();

        #pragma unroll
        for (int a = 0; a < 4; a++) {
            float s = sA[i0+a];
            #pragma unroll
            for (int c = 0; c < 4; c++) o[a][c] *= s;
        }
        #pragma unroll 8
        for (int s = 0; s < 64; s++) {
            float4 vv = *(const float4*)(Vs + s*64 + j0);
            float vr[4] = {vv.x,vv.y,vv.z,vv.w};
            float p0 = Ss[(i0+0)*68+s], p1 = Ss[(i0+1)*68+s];
            float p2 = Ss[(i0+2)*68+s], p3 = Ss[(i0+3)*68+s];
            #pragma unroll
            for (int c = 0; c < 4; c++) {
                o[0][c]+=p0*vr[c]; o[1][c]+=p1*vr[c]; o[2][c]+=p2*vr[c]; o[3][c]+=p3*vr[c];
            }
        }
        __syncthreads();
    }
    #pragma unroll
    for (int a = 0; a < 4; a++) {
        float inv = 1.f / lA[i0+a];
        float4 v = make_float4(o[a][0]*inv, o[a][1]*inv, o[a][2]*inv, o[a][3]*inv);
        *(float4*)(g_o + (size_t)(b*SEQ + q0 + i0 + a)*D_MODEL + h*64 + j0) = v;
    }
}

// ---------------- launch ----------------
extern "C" void kernel_launch(void* const* d_in, const int* in_sizes, int n_in,
                              void* d_out, int out_size)
{
    const int*   x     = (const int*)  d_in[0];
    const float* tok   = (const float*)d_in[1];
    const float* pos   = (const float*)d_in[2];
    const float* Wq    = (const float*)d_in[3];
    const float* Wk    = (const float*)d_in[4];
    const float* Wv    = (const float*)d_in[5];
    const float* Wproj = (const float*)d_in[6];
    const float* bproj = (const float*)d_in[7];
    const float* ln1_g = (const float*)d_in[8];
    const float* ln1_b = (const float*)d_in[9];
    const float* ln2_g = (const float*)d_in[10];
    const float* ln2_b = (const float*)d_in[11];
    const float* W1    = (const float*)d_in[12];
    const float* b1    = (const float*)d_in[13];
    const float* W2    = (const float*)d_in[14];
    const float* b2    = (const float*)d_in[15];
    const float* lnf_g = (const float*)d_in[16];
    const float* lnf_b = (const float*)d_in[17];
    const float* Wlm   = (const float*)d_in[18];
    const float* blm   = (const float*)d_in[19];
    float* out = (float*)d_out;

    float *h_, *ln_, *qkv_, *o_, *f_;
    __half *qT, *pT, *w1p, *w2p, *lmp;
    cudaGetSymbolAddress((void**)&h_,  g_h);
    cudaGetSymbolAddress((void**)&ln_, g_ln);
    cudaGetSymbolAddress((void**)&qkv_,g_qkv);
    cudaGetSymbolAddress((void**)&o_,  g_o);
    cudaGetSymbolAddress((void**)&f_,  g_f);
    cudaGetSymbolAddress((void**)&qT,  g_qT);
    cudaGetSymbolAddress((void**)&pT,  g_pT);
    cudaGetSymbolAddress((void**)&w1p, g_w1);
    cudaGetSymbolAddress((void**)&w2p, g_w2);
    cudaGetSymbolAddress((void**)&lmp, g_lm);

    cudaFuncSetAttribute(gemm_mma<false,false,false>, cudaFuncAttributeMaxDynamicSharedMemorySize, GSMEM);
    cudaFuncSetAttribute(gemm_mma<true,false,true>,   cudaFuncAttributeMaxDynamicSharedMemorySize, GSMEM);
    cudaFuncSetAttribute(gemm_mma<true,true,false>,   cudaFuncAttributeMaxDynamicSharedMemorySize, GSMEM);
    cudaFuncSetAttribute(gemm_mma<true,false,false>,  cudaFuncAttributeMaxDynamicSharedMemorySize, GSMEM);
    cudaFuncSetAttribute(attn2, cudaFuncAttributeMaxDynamicSharedMemorySize, ASM_TOT);

    dim3 tb(32, 8);
    qkv_repack<<<dim3(2, 32, NLAYER*48), tb>>>(Wq, Wk, Wv);
    transpose_cvt<<<dim3(32, 32, NLAYER), tb>>>(Wproj, pT, D_MODEL, D_MODEL,
        (size_t)D_MODEL*D_MODEL, (size_t)D_MODEL*D_MODEL);
    transpose_cvt<<<dim3(128, 32, NLAYER), tb>>>(W1, w1p, D_MODEL, DFF,
        (size_t)D_MODEL*DFF, (size_t)D_MODEL*DFF);
    transpose_cvt<<<dim3(32, 128, NLAYER), tb>>>(W2, w2p, DFF, D_MODEL,
        (size_t)D_MODEL*DFF, (size_t)D_MODEL*DFF);
    transpose_cvt<<<dim3(1000, 32, 1), tb>>>(Wlm, lmp, D_MODEL, VOCAB, 0, 0);

    embed_kernel<<<(BT*D_MODEL)/256, 256>>>(x, tok, pos);

    for (int l = 0; l < NLAYER; l++) {
        ln_kernel<<<BT, 256>>>(h_, ln1_g + (size_t)l*D_MODEL, ln1_b + (size_t)l*D_MODEL, ln_);
        gemm_mma<false,false,false><<<dim3(BT/128, 3*D_MODEL/128), 256, GSMEM>>>(
            ln_, qT + (size_t)l*3*D_MODEL*D_MODEL, nullptr, nullptr, qkv_,
            BT, 3*D_MODEL, D_MODEL);
        attn2<<<dim3(SEQ/64, BATCH*NHEAD), 256, ASM_TOT>>>();
        gemm_mma<true,false,true><<<dim3(BT/128, D_MODEL/128), 256, GSMEM>>>(
            o_, pT + (size_t)l*D_MODEL*D_MODEL, bproj + (size_t)l*D_MODEL, h_, h_,
            BT, D_MODEL, D_MODEL);
        ln_kernel<<<BT, 256>>>(h_, ln2_g + (size_t)l*D_MODEL, ln2_b + (size_t)l*D_MODEL, ln_);
        gemm_mma<true,true,false><<<dim3(BT/128, DFF/128), 256, GSMEM>>>(
            ln_, w1p + (size_t)l*D_MODEL*DFF, b1 + (size_t)l*DFF, nullptr, f_,
            BT, DFF, D_MODEL);
        gemm_mma<true,false,true><<<dim3(BT/128, D_MODEL/128), 256, GSMEM>>>(
            f_, w2p + (size_t)l*D_MODEL*DFF, b2 + (size_t)l*D_MODEL, h_, h_,
            BT, D_MODEL, DFF);
    }

    ln_kernel<<<BT, 256>>>(h_, lnf_g, lnf_b, ln_);
    gemm_mma<true,false,false><<<dim3(BT/128, VOCAB/128), 256, GSMEM>>>(
        ln_, lmp, blm, nullptr, out, BT, VOCAB, D_MODEL);
}